// round 6
// baseline (speedup 1.0000x reference)
#include <cuda_runtime.h>
#include <cstdint>

// Problem constants
#define HH 14
#define WWD 14
#define HW 196
#define CH 512
#define NCHAIN 8     // 4 modes x 2 batches
#define CLUS 8       // CTAs per cluster (one chain)
#define NTHR 512

// Dynamic smem layout (bytes)
#define OFF_GHIST 0
#define OFF_SLAB  (32 * CH * 4)              // 65536
#define OFF_PSLOT (OFF_SLAB + 16 * CH * 4)   // 98304
#define OFF_GSLOT (OFF_PSLOT + 8 * 64 * 4)   // 100352
#define OFF_HCH   (OFF_GSLOT + 2 * 8 * CH * 4) // 133120
#define OFF_ASMEM (OFF_HCH + 64 * 4)           // 133376
#define OFF_FLAGS (OFF_ASMEM + 2 * CH * 4)     // 137472
#define SMEM_SZ   (OFF_FLAGS + 2 * 16 * 4)     // 137600

// Static device scratch
__device__ float g_A0[2 * HW * CH];      // Wx@input + b_in, [b][pixel][c]
__device__ float g_Hv[NCHAIN * HW * CH]; // h_vi history for epilogue

__device__ __forceinline__ float4 relu4(float4 a) {
    return make_float4(fmaxf(a.x, 0.f), fmaxf(a.y, 0.f),
                       fmaxf(a.z, 0.f), fmaxf(a.w, 0.f));
}
__device__ __forceinline__ float4 add4(float4 a, float4 b) {
    return make_float4(a.x + b.x, a.y + b.y, a.z + b.z, a.w + b.w);
}
__device__ __forceinline__ float max4(float4 a) {
    return fmaxf(fmaxf(a.x, a.y), fmaxf(a.z, a.w));
}
__device__ __forceinline__ float sum4(float4 a) {
    return (a.x + a.y) + (a.z + a.w);
}
__device__ __forceinline__ float4 exp4(float4 a, float m) {
    return make_float4(__expf(a.x - m), __expf(a.y - m),
                       __expf(a.z - m), __expf(a.w - m));
}
__device__ __forceinline__ float warp_max(float v) {
#pragma unroll
    for (int o = 16; o; o >>= 1)
        v = fmaxf(v, __shfl_xor_sync(0xffffffffu, v, o));
    return v;
}
__device__ __forceinline__ float warp_sum(float v) {
#pragma unroll
    for (int o = 16; o; o >>= 1)
        v += __shfl_xor_sync(0xffffffffu, v, o);
    return v;
}
__device__ __forceinline__ uint32_t s2u(const void* p) {
    uint32_t a;
    asm("{ .reg .u64 t; cvta.to.shared.u64 t, %1; cvt.u32.u64 %0, t; }"
        : "=r"(a) : "l"(p));
    return a;
}
__device__ __forceinline__ void st_cluster_f32(uint32_t laddr, uint32_t rnk, float v) {
    uint32_t ra;
    asm("mapa.shared::cluster.u32 %0, %1, %2;" : "=r"(ra) : "r"(laddr), "r"(rnk));
    asm volatile("st.shared::cluster.f32 [%0], %1;" :: "r"(ra), "f"(v) : "memory");
}
__device__ __forceinline__ unsigned long long fma2(unsigned long long a,
                                                   unsigned long long b,
                                                   unsigned long long c) {
    unsigned long long d;
    asm("fma.rn.f32x2 %0, %1, %2, %3;" : "=l"(d) : "l"(a), "l"(b), "l"(c));
    return d;
}
__device__ __forceinline__ float unpack_sum(unsigned long long a) {
    float lo, hi;
    asm("mov.b64 {%0, %1}, %2;" : "=f"(lo), "=f"(hi) : "l"(a));
    return lo + hi;
}
#define CLUSTER_ARRIVE() asm volatile("barrier.cluster.arrive.aligned;" ::: "memory")
#define CLUSTER_WAIT()   asm volatile("barrier.cluster.wait.aligned;"   ::: "memory")

struct C4 { float4 v0, v1, v2, v3; };

// Per-cell softmax-pool contribution from explicit a,g registers.
__device__ __forceinline__ C4 pool_cell(float4 a0, float4 a1, float4 a2, float4 a3,
                                        float4 g0, float4 g1, float4 g2, float4 g3) {
    float4 z0 = relu4(add4(a0, g0)), z1 = relu4(add4(a1, g1));
    float4 z2 = relu4(add4(a2, g2)), z3 = relu4(add4(a3, g3));
    float m = warp_max(fmaxf(fmaxf(max4(z0), max4(z1)), fmaxf(max4(z2), max4(z3))));
    float4 e0 = exp4(z0, m), e1 = exp4(z1, m);
    float4 e2 = exp4(z2, m), e3 = exp4(z3, m);
    float es = warp_sum(sum4(e0) + sum4(e1) + sum4(e2) + sum4(e3));
    float inv = __fdividef(1.f, es);
    C4 r;
    r.v0 = make_float4(z0.x * e0.x * inv, z0.y * e0.y * inv, z0.z * e0.z * inv, z0.w * e0.w * inv);
    r.v1 = make_float4(z1.x * e1.x * inv, z1.y * e1.y * inv, z1.z * e1.z * inv, z1.w * e1.w * inv);
    r.v2 = make_float4(z2.x * e2.x * inv, z2.y * e2.y * inv, z2.z * e2.z * inv, z2.w * e2.w * inv);
    r.v3 = make_float4(z3.x * e3.x * inv, z3.y * e3.y * inv, z3.z * e3.z * inv, z3.w * e3.w * inv);
    return r;
}

// ---------------------------------------------------------------------------
// Prologue: A0[b][p][c] = sum_k Wx[c,k]*input[b,k,p] + b_in[c]
// ---------------------------------------------------------------------------
__global__ __launch_bounds__(NTHR) void prologue_kernel(
    const float* __restrict__ input, const float* __restrict__ Wx,
    const float* __restrict__ b_in) {
    __shared__ float xs[4 * 520];
    const int tid = threadIdx.x;
    const int b   = blockIdx.x / 49;
    const int p0  = (blockIdx.x % 49) * 4;
#pragma unroll
    for (int j = 0; j < 4; j++)
        xs[j * 520 + tid] = input[(size_t)(b * CH + tid) * HW + p0 + j];
    __syncthreads();
    const float4* w4 = (const float4*)(Wx + (size_t)tid * CH);
    float acc[4] = {0.f, 0.f, 0.f, 0.f};
    for (int k4 = 0; k4 < CH / 4; k4++) {
        float4 w = w4[k4];
#pragma unroll
        for (int j = 0; j < 4; j++) {
            float4 x = *(const float4*)(xs + j * 520 + 4 * k4);
            acc[j] += w.x * x.x + w.y * x.y + w.z * x.z + w.w * x.w;
        }
    }
    float bb = b_in[tid];
#pragma unroll
    for (int j = 0; j < 4; j++)
        g_A0[(size_t)(b * HW + p0 + j) * CH + tid] = acc[j] + bb;
}

// ---------------------------------------------------------------------------
// Scan: one 8-CTA cluster per chain, 196 sequential steps. All cross-CTA
// traffic through DSMEM. k-chunked matvec (thread = row, CTA = k-chunk),
// owner-side lazy G finalization, sparse flagged slab reduce.
// ---------------------------------------------------------------------------
__global__ void __cluster_dims__(CLUS, 1, 1) __launch_bounds__(NTHR, 1)
scan_kernel(const float* __restrict__ Wh) {
    extern __shared__ char smem[];
    const uint32_t sbase = s2u(smem);
    float* ghist = (float*)(smem + OFF_GHIST);   // 32 owned-cell slots x 512
    float* slab  = (float*)(smem + OFF_SLAB);    // 16 x 512 warp contributions
    float* pslot = (float*)(smem + OFF_PSLOT);   // 8 x 64 received h partial-chunks
    float* gslot = (float*)(smem + OFF_GSLOT);   // 2 x 8 x 512 received G partials
    float* hch   = (float*)(smem + OFF_HCH);     // 64 reduced h chunk
    float* asmem = (float*)(smem + OFF_ASMEM);   // ping-pong a buffers
    int*   flags = (int*)(smem + OFF_FLAGS);     // 2 x 16 active-warp flags

    const int tid  = threadIdx.x;
    const int wid  = tid >> 5, lane = tid & 31;
    const int rank = blockIdx.x & 7;
    const int chain = blockIdx.x >> 3;
    const int mode = chain >> 1, bb = chain & 1;
    const int gw = rank * 16 + wid;              // cluster-wide warp id 0..127
    const int c1 = gw, c2 = gw + 128;
    const int cx1 = c1 / WWD, cy1 = c1 - cx1 * WWD;
    const int cx2 = c2 / WWD, cy2 = c2 - cx2 * WWD;
    const bool has2 = (c2 < HW);

    // Weights: thread = row tid, k-chunk = [rank*64, rank*64+64) as f32x2 pairs
    unsigned long long wreg2[32];
    {
        const unsigned long long* Wr =
            (const unsigned long long*)(Wh + (size_t)tid * CH + rank * 64);
#pragma unroll
        for (int j = 0; j < 32; j++) wreg2[j] = Wr[j];
    }

    const float* Ab = g_A0 + (size_t)bb * HW * CH;
    float* Hc = g_Hv + (size_t)chain * HW * CH;

    if (tid < 32) flags[tid] = 0;
    {   // a(p=0) -> asmem buf 0
        int fx = (mode & 2) ? (HH - 1) : 0;
        int fy = (mode & 1) ? (WWD - 1) : 0;
        asmem[tid] = __ldg(Ab + (size_t)(fx * WWD + fy) * CH + tid);
    }
    __syncthreads();

    float4* myslab = (float4*)(slab + wid * CH);
    const float4 zz = make_float4(0.f, 0.f, 0.f, 0.f);

    for (int p = 0; p < HW; p++) {
        const int px = p / WWD, py = p - px * WWD;
        const float4* aps = (const float4*)(asmem + (p & 1) * CH);
        float4 a0 = aps[lane],      a1 = aps[lane + 32];
        float4 a2 = aps[lane + 64], a3 = aps[lane + 96];

        const bool act1 = (cx1 <= px) && (cy1 <= py);
        const bool act2 = has2 && (cx2 <= px) && (cy2 <= py);
        const bool fin1 = (p > 0) && (c1 == p - 1);          // cell to finalize
        const bool fin2 = (p > 0) && has2 && (c2 == p - 1);

        // ---- non-deferred cells (G already finalized in ghist, or cell==p) ----
        C4 acc; acc.v0 = zz; acc.v1 = zz; acc.v2 = zz; acc.v3 = zz;
        bool any = false;
        if (act1 && !fin1) {
            float4 g0 = zz, g1 = zz, g2 = zz, g3 = zz;
            if (c1 != p) {
                int slot = (c1 & 15) + ((c1 >> 7) << 4);
                const float4* g4 = (const float4*)(ghist + slot * CH);
                g0 = g4[lane]; g1 = g4[lane + 32]; g2 = g4[lane + 64]; g3 = g4[lane + 96];
            }
            acc = pool_cell(a0, a1, a2, a3, g0, g1, g2, g3); any = true;
        }
        if (act2 && !fin2) {
            float4 g0 = zz, g1 = zz, g2 = zz, g3 = zz;
            if (c2 != p) {
                int slot = (c2 & 15) + ((c2 >> 7) << 4);
                const float4* g4 = (const float4*)(ghist + slot * CH);
                g0 = g4[lane]; g1 = g4[lane + 32]; g2 = g4[lane + 64]; g3 = g4[lane + 96];
            }
            C4 r = pool_cell(a0, a1, a2, a3, g0, g1, g2, g3);
            if (any) { acc.v0 = add4(acc.v0, r.v0); acc.v1 = add4(acc.v1, r.v1);
                       acc.v2 = add4(acc.v2, r.v2); acc.v3 = add4(acc.v3, r.v3); }
            else acc = r;
            any = true;
        }

        if (p > 0) CLUSTER_WAIT();     // R2(p-1): G partial scatter of cell p-1 done

        // ---- owner warp: finalize cell p-1 (sum 8 partials), maybe contribute ----
        if (fin1 | fin2) {
            const float* gs = gslot + ((p - 1) & 1) * 8 * CH;
            float4 s0 = zz, s1 = zz, s2 = zz, s3 = zz;
#pragma unroll
            for (int r = 0; r < 8; r++) {
                const float4* gr = (const float4*)(gs + r * CH);
                s0 = add4(s0, gr[lane]);      s1 = add4(s1, gr[lane + 32]);
                s2 = add4(s2, gr[lane + 64]); s3 = add4(s3, gr[lane + 96]);
            }
            int fc = p - 1;
            int slot = (fc & 15) + ((fc >> 7) << 4);
            float4* gh = (float4*)(ghist + slot * CH);
            gh[lane] = s0; gh[lane + 32] = s1; gh[lane + 64] = s2; gh[lane + 96] = s3;
            if ((fin1 && act1) || (fin2 && act2)) {
                C4 r = pool_cell(a0, a1, a2, a3, s0, s1, s2, s3);
                if (any) { acc.v0 = add4(acc.v0, r.v0); acc.v1 = add4(acc.v1, r.v1);
                           acc.v2 = add4(acc.v2, r.v2); acc.v3 = add4(acc.v3, r.v3); }
                else acc = r;
                any = true;
            }
        }

        if (any) {
            myslab[lane] = acc.v0; myslab[lane + 32] = acc.v1;
            myslab[lane + 64] = acc.v2; myslab[lane + 96] = acc.v3;
            if (lane == 0) flags[(p & 1) * 16 + wid] = 1;
        }
        __syncthreads();                       // slab + flags ready

        // ---- sparse CTA reduce -> partial; reduce-scatter via DSMEM ----
        {
            const int* fl = flags + (p & 1) * 16;
            float part = 0.f;
#pragma unroll
            for (int w = 0; w < 16; w++)
                if (fl[w]) part += slab[w * CH + tid];
            // send channel tid to CTA tid>>6, slot [rank][tid&63]
            uint32_t laddr = sbase + OFF_PSLOT + (uint32_t)((rank * 64 + (tid & 63)) * 4);
            st_cluster_f32(laddr, (uint32_t)(tid >> 6), part);
        }
        if (tid < 16) flags[((p + 1) & 1) * 16 + tid] = 0;
        CLUSTER_ARRIVE();                      // R1 arrive (releases pslot writes)

        // prefetch a(p+1) (hides behind R1 wait)
        if (p + 1 < HW) {
            int pn = p + 1, pxn = pn / WWD, pyn = pn - pxn * WWD;
            int fx = (mode & 2) ? (HH - 1 - pxn) : pxn;
            int fy = (mode & 1) ? (WWD - 1 - pyn) : pyn;
            asmem[((p + 1) & 1) * CH + tid] =
                __ldg(Ab + (size_t)(fx * WWD + fy) * CH + tid);
        }
        CLUSTER_WAIT();                        // R1 wait (acquires pslot)
        __syncthreads();                       // intra-CTA: flags/asmem ordering

        // ---- sum 8 received chunks -> h_chunk (threads 0..63) ----
        if (tid < 64) {
            float h = 0.f;
#pragma unroll
            for (int r = 0; r < 8; r++) h += pslot[r * 64 + tid];
            hch[tid] = h;
            Hc[(size_t)p * CH + rank * 64 + tid] = h;   // history for epilogue
        }
        __syncthreads();                       // h_chunk ready

        // ---- partial matvec: Gpart[tid] = Wh[tid, chunk] . h_chunk ----
        {
            const ulonglong2* h2 = (const ulonglong2*)hch;   // broadcast reads
            unsigned long long q0 = 0ull, q1 = 0ull, q2 = 0ull, q3 = 0ull;
#pragma unroll
            for (int j2 = 0; j2 < 16; j2 += 2) {
                ulonglong2 ha = h2[j2], hb = h2[j2 + 1];
                q0 = fma2(wreg2[2 * j2 + 0], ha.x, q0);
                q1 = fma2(wreg2[2 * j2 + 1], ha.y, q1);
                q2 = fma2(wreg2[2 * j2 + 2], hb.x, q2);
                q3 = fma2(wreg2[2 * j2 + 3], hb.y, q3);
            }
            float g = (unpack_sum(q0) + unpack_sum(q1)) +
                      (unpack_sum(q2) + unpack_sum(q3));
            // scatter to owner of cell p, buffer p&1, slot [rank][tid]
            uint32_t orank = (uint32_t)((p & 127) >> 4);
            uint32_t laddr = sbase + OFF_GSLOT +
                             (uint32_t)(((p & 1) * 8 * CH + rank * CH + tid) * 4);
            st_cluster_f32(laddr, orank, g);
        }
        CLUSTER_ARRIVE();                      // R2 arrive (releases G partials)
    }
    CLUSTER_WAIT();                            // close final generation
}

// ---------------------------------------------------------------------------
// Fused epilogue: Y = Wo @ (sum_m Hv) + 4*b_out, then channel softmax -> out
// ---------------------------------------------------------------------------
__global__ __launch_bounds__(NTHR) void epilogue_kernel(
    const float* __restrict__ Wo, const float* __restrict__ b_out,
    float* __restrict__ out) {
    __shared__ float hs[4 * 520];
    __shared__ float red[16];
    const int tid = threadIdx.x;
    const int wid = tid >> 5, lane = tid & 31;
    const int b   = blockIdx.x / 49;
    const int p0  = (blockIdx.x % 49) * 4;
#pragma unroll
    for (int j = 0; j < 4; j++) {
        float s = 0.f;
#pragma unroll
        for (int m = 0; m < 4; m++)
            s += g_Hv[((size_t)(m * 2 + b) * HW + p0 + j) * CH + tid];
        hs[j * 520 + tid] = s;
    }
    __syncthreads();
    const float4* w4 = (const float4*)(Wo + (size_t)tid * CH);
    float acc[4] = {0.f, 0.f, 0.f, 0.f};
    for (int k4 = 0; k4 < CH / 4; k4++) {
        float4 w = w4[k4];
#pragma unroll
        for (int j = 0; j < 4; j++) {
            float4 h = *(const float4*)(hs + j * 520 + 4 * k4);
            acc[j] += w.x * h.x + w.y * h.y + w.z * h.z + w.w * h.w;
        }
    }
    float bo = 4.f * b_out[tid];
#pragma unroll
    for (int j = 0; j < 4; j++) acc[j] += bo;

    // channel softmax per pixel j (512 threads = channels)
#pragma unroll
    for (int j = 0; j < 4; j++) {
        float m = warp_max(acc[j]);
        if (lane == 0) red[wid] = m;
        __syncthreads();
        float mm = red[0];
#pragma unroll
        for (int k = 1; k < 16; k++) mm = fmaxf(mm, red[k]);
        float e = __expf(acc[j] - mm);
        __syncthreads();
        float s = warp_sum(e);
        if (lane == 0) red[wid] = s;
        __syncthreads();
        float ss = 0.f;
#pragma unroll
        for (int k = 0; k < 16; k++) ss += red[k];
        out[((size_t)b * CH + tid) * HW + p0 + j] = e / ss;
        __syncthreads();
    }
}

extern "C" void kernel_launch(void* const* d_in, const int* in_sizes, int n_in,
                              void* d_out, int out_size) {
    const float* input = (const float*)d_in[0];
    const float* Wx    = (const float*)d_in[1];
    const float* Wh    = (const float*)d_in[2];
    const float* b_in  = (const float*)d_in[3];
    const float* Wo    = (const float*)d_in[4];
    const float* b_out = (const float*)d_in[5];
    float* out = (float*)d_out;
    (void)in_sizes; (void)n_in; (void)out_size;

    cudaFuncSetAttribute(scan_kernel,
                         cudaFuncAttributeMaxDynamicSharedMemorySize, SMEM_SZ);

    prologue_kernel<<<98, NTHR>>>(input, Wx, b_in);
    scan_kernel<<<NCHAIN * CLUS, NTHR, SMEM_SZ>>>(Wh);
    epilogue_kernel<<<98, NTHR>>>(Wo, b_out, out);
}

// round 7
// speedup vs baseline: 1.2594x; 1.2594x over previous
#include <cuda_runtime.h>
#include <cstdint>

// Problem constants
#define HH 14
#define WWD 14
#define HW 196
#define CH 512
#define NCHAIN 8     // 4 modes x 2 batches
#define CLUS 8       // CTAs per cluster (one chain)
#define NTHR 512
#define PAY 640      // floats per payload slot: 512 part + 64 num + m + s + pad

// Dynamic smem layout (bytes)
#define OFF_GHIST 0                    // 25 slots x 512 x 4 = 51200
#define OFF_SLAB  51200                // 16 x 512 x 4      = 32768
#define OFF_XSLOT 83968                // 2 x 8 x 640 x 4   = 40960
#define OFF_HVEC  124928               // 512 x 4           = 2048
#define OFF_ZBUF  126976               // 64 x 4            = 256
#define OFF_SCR   127232               // 16 x 4            = 64
#define OFF_ASMEM 127296               // 2 x 512 x 4       = 4096
#define OFF_FLAGS 131392               // 2 x 16 x 4        = 128
#define SMEM_SZ   131520

// Static device scratch
__device__ float g_A0[2 * HW * CH];      // Wx@input + b_in, [b][pixel][c]
__device__ float g_Hv[NCHAIN * HW * CH]; // h_vi history for epilogue

__device__ __forceinline__ float4 relu4(float4 a) {
    return make_float4(fmaxf(a.x, 0.f), fmaxf(a.y, 0.f),
                       fmaxf(a.z, 0.f), fmaxf(a.w, 0.f));
}
__device__ __forceinline__ float4 add4(float4 a, float4 b) {
    return make_float4(a.x + b.x, a.y + b.y, a.z + b.z, a.w + b.w);
}
__device__ __forceinline__ float max4(float4 a) {
    return fmaxf(fmaxf(a.x, a.y), fmaxf(a.z, a.w));
}
__device__ __forceinline__ float sum4(float4 a) {
    return (a.x + a.y) + (a.z + a.w);
}
__device__ __forceinline__ float dot4(float4 a, float4 b) {
    return a.x * b.x + a.y * b.y + a.z * b.z + a.w * b.w;
}
__device__ __forceinline__ float4 exp4(float4 a, float m) {
    return make_float4(__expf(a.x - m), __expf(a.y - m),
                       __expf(a.z - m), __expf(a.w - m));
}
__device__ __forceinline__ float warp_max(float v) {
#pragma unroll
    for (int o = 16; o; o >>= 1)
        v = fmaxf(v, __shfl_xor_sync(0xffffffffu, v, o));
    return v;
}
__device__ __forceinline__ float warp_sum(float v) {
#pragma unroll
    for (int o = 16; o; o >>= 1)
        v += __shfl_xor_sync(0xffffffffu, v, o);
    return v;
}
__device__ __forceinline__ uint32_t s2u(const void* p) {
    uint32_t a;
    asm("{ .reg .u64 t; cvta.to.shared.u64 t, %1; cvt.u32.u64 %0, t; }"
        : "=r"(a) : "l"(p));
    return a;
}
__device__ __forceinline__ void st_cluster_f32(uint32_t laddr, uint32_t rnk, float v) {
    uint32_t ra;
    asm("mapa.shared::cluster.u32 %0, %1, %2;" : "=r"(ra) : "r"(laddr), "r"(rnk));
    asm volatile("st.shared::cluster.f32 [%0], %1;" :: "r"(ra), "f"(v) : "memory");
}
#define CLUSTER_ARRIVE() asm volatile("barrier.cluster.arrive.aligned;" ::: "memory")
#define CLUSTER_WAIT()   asm volatile("barrier.cluster.wait.aligned;"   ::: "memory")

struct C4 { float4 v0, v1, v2, v3; };

// Softmax-pool of one cell: whole warp = 512 channels, 16/lane.
__device__ __forceinline__ C4 pool_cell(float4 a0, float4 a1, float4 a2, float4 a3,
                                        float4 g0, float4 g1, float4 g2, float4 g3) {
    float4 z0 = relu4(add4(a0, g0)), z1 = relu4(add4(a1, g1));
    float4 z2 = relu4(add4(a2, g2)), z3 = relu4(add4(a3, g3));
    float m = warp_max(fmaxf(fmaxf(max4(z0), max4(z1)), fmaxf(max4(z2), max4(z3))));
    float4 e0 = exp4(z0, m), e1 = exp4(z1, m);
    float4 e2 = exp4(z2, m), e3 = exp4(z3, m);
    float es = warp_sum(sum4(e0) + sum4(e1) + sum4(e2) + sum4(e3));
    float inv = __fdividef(1.f, es);
    C4 r;
    r.v0 = make_float4(z0.x * e0.x * inv, z0.y * e0.y * inv, z0.z * e0.z * inv, z0.w * e0.w * inv);
    r.v1 = make_float4(z1.x * e1.x * inv, z1.y * e1.y * inv, z1.z * e1.z * inv, z1.w * e1.w * inv);
    r.v2 = make_float4(z2.x * e2.x * inv, z2.y * e2.y * inv, z2.z * e2.z * inv, z2.w * e2.w * inv);
    r.v3 = make_float4(z3.x * e3.x * inv, z3.y * e3.y * inv, z3.z * e3.z * inv, z3.w * e3.w * inv);
    return r;
}

// Reconstruct full h(q) from the 8 payloads (partials + online-softmax JIT cell).
__device__ __forceinline__ void reconstruct(int q, int tid, int rank,
                                            const float* xslot, float* hvec,
                                            float* gHc) {
    const float* xs = xslot + (q & 1) * 8 * PAY;
    float h = 0.f;
#pragma unroll
    for (int r = 0; r < 8; r++) h += xs[r * PAY + tid];
    if ((q % WWD) >= 1) {   // JIT cell q-1 was pooled distributed at step q
        float m0 = xs[0 * PAY + 576], m1 = xs[1 * PAY + 576];
        float m2 = xs[2 * PAY + 576], m3 = xs[3 * PAY + 576];
        float m4 = xs[4 * PAY + 576], m5 = xs[5 * PAY + 576];
        float m6 = xs[6 * PAY + 576], m7 = xs[7 * PAY + 576];
        float M = fmaxf(fmaxf(fmaxf(m0, m1), fmaxf(m2, m3)),
                        fmaxf(fmaxf(m4, m5), fmaxf(m6, m7)));
        float D = xs[0 * PAY + 577] * __expf(m0 - M)
                + xs[1 * PAY + 577] * __expf(m1 - M)
                + xs[2 * PAY + 577] * __expf(m2 - M)
                + xs[3 * PAY + 577] * __expf(m3 - M)
                + xs[4 * PAY + 577] * __expf(m4 - M)
                + xs[5 * PAY + 577] * __expf(m5 - M)
                + xs[6 * PAY + 577] * __expf(m6 - M)
                + xs[7 * PAY + 577] * __expf(m7 - M);
        int rs = tid >> 6;                           // warp-uniform
        float num  = xs[rs * PAY + 512 + (tid & 63)];
        float msel = xs[rs * PAY + 576];
        h += num * __expf(msel - M) * __fdividef(1.f, D);
    }
    hvec[tid] = h;
    if (rank == (q & 7)) gHc[(size_t)q * CH + tid] = h;
}

// ---------------------------------------------------------------------------
// Prologue: A0[b][p][c] = sum_k Wx[c,k]*input[b,k,p] + b_in[c]
// ---------------------------------------------------------------------------
__global__ __launch_bounds__(NTHR) void prologue_kernel(
    const float* __restrict__ input, const float* __restrict__ Wx,
    const float* __restrict__ b_in) {
    __shared__ float xs[4 * 520];
    const int tid = threadIdx.x;
    const int b   = blockIdx.x / 49;
    const int p0  = (blockIdx.x % 49) * 4;
#pragma unroll
    for (int j = 0; j < 4; j++)
        xs[j * 520 + tid] = input[(size_t)(b * CH + tid) * HW + p0 + j];
    __syncthreads();
    const float4* w4 = (const float4*)(Wx + (size_t)tid * CH);
    float acc[4] = {0.f, 0.f, 0.f, 0.f};
    for (int k4 = 0; k4 < CH / 4; k4++) {
        float4 w = w4[k4];
#pragma unroll
        for (int j = 0; j < 4; j++) {
            float4 x = *(const float4*)(xs + j * 520 + 4 * k4);
            acc[j] += w.x * x.x + w.y * x.y + w.z * x.z + w.w * x.w;
        }
    }
    float bb = b_in[tid];
#pragma unroll
    for (int j = 0; j < 4; j++)
        g_A0[(size_t)(b * HW + p0 + j) * CH + tid] = acc[j] + bb;
}

// ---------------------------------------------------------------------------
// Scan: one 8-CTA cluster per chain, 196 steps, ONE cluster-barrier round/step.
// ---------------------------------------------------------------------------
__global__ void __cluster_dims__(CLUS, 1, 1) __launch_bounds__(NTHR, 1)
scan_kernel(const float* __restrict__ Wh) {
    extern __shared__ char smem[];
    const uint32_t sbase = s2u(smem);
    float* ghist = (float*)(smem + OFF_GHIST);
    float* slab  = (float*)(smem + OFF_SLAB);
    float* xslot = (float*)(smem + OFF_XSLOT);
    float* hvec  = (float*)(smem + OFF_HVEC);
    float* zbuf  = (float*)(smem + OFF_ZBUF);
    float* scr   = (float*)(smem + OFF_SCR);
    float* asmem = (float*)(smem + OFF_ASMEM);
    int*   flags = (int*)(smem + OFF_FLAGS);

    const int tid  = threadIdx.x;
    const int wid  = tid >> 5, lane = tid & 31;
    const int rank = blockIdx.x & 7;
    const int chain = blockIdx.x >> 3;
    const int mode = chain >> 1, bb = chain & 1;

    // Owned cells: owner rank = c&7 (balanced), warp = (c>>3)&15
    const int c1o = rank + 8 * wid;
    const int c2o = c1o + 128;
    const int c1x = c1o / WWD, c1y = c1o - c1x * WWD;
    const int c2x = c2o / WWD, c2y = c2o - c2x * WWD;
    const bool has2 = (c2o < HW);

    // Matvec rows R..R+3 per warp; lane holds channels 4*lane + 128*k
    const int R = 64 * rank + 4 * wid;
    float4 wreg[4][4];
#pragma unroll
    for (int i = 0; i < 4; i++)
#pragma unroll
        for (int k = 0; k < 4; k++)
            wreg[i][k] = *(const float4*)(Wh + (size_t)(R + i) * CH + 4 * lane + 128 * k);

    const float* Ab = g_A0 + (size_t)bb * HW * CH;
    float* gHc = g_Hv + (size_t)chain * HW * CH;

    if (tid < 32) flags[tid] = 0;
    {   // a(0)
        int fx = (mode & 2) ? (HH - 1) : 0;
        int fy = (mode & 1) ? (WWD - 1) : 0;
        asmem[tid] = __ldg(Ab + (size_t)(fx * WWD + fy) * CH + tid);
    }
    __syncthreads();

    float4* myslab = (float4*)(slab + wid * CH);
    const float4 zz4 = make_float4(0.f, 0.f, 0.f, 0.f);

    for (int p = 0; p < HW; p++) {
        const int px = p / WWD, py = p - px * WWD;

        // ---------- PRE-WAIT ----------
        const float4* aps = (const float4*)(asmem + (p & 1) * CH);
        float4 a0 = aps[lane],      a1 = aps[lane + 32];
        float4 a2 = aps[lane + 64], a3 = aps[lane + 96];

        C4 acc; acc.v0 = zz4; acc.v1 = zz4; acc.v2 = zz4; acc.v3 = zz4;
        bool any = false;
        int dcell = -1;   // deferred cell (== p-2, visible after wait)
#pragma unroll
        for (int ci = 0; ci < 2; ci++) {
            int c  = ci ? c2o : c1o;
            int cx = ci ? c2x : c1x;
            int cy = ci ? c2y : c1y;
            bool inw = (ci == 0 || has2) && (cx <= px) && (cy <= py);
            if (!inw) continue;
            if (c == p) {
                C4 r = pool_cell(a0, a1, a2, a3, zz4, zz4, zz4, zz4);
                if (any) { acc.v0 = add4(acc.v0, r.v0); acc.v1 = add4(acc.v1, r.v1);
                           acc.v2 = add4(acc.v2, r.v2); acc.v3 = add4(acc.v3, r.v3); }
                else acc = r;
                any = true;
            } else if (c == p - 1) {
                // JIT cell: handled distributed (numerators), skip here
            } else if (c == p - 2) {
                dcell = c;                       // pool post-wait
            } else {
                const float4* g4 = (const float4*)(ghist + (c >> 3) * CH);
                C4 r = pool_cell(a0, a1, a2, a3,
                                 g4[lane], g4[lane + 32], g4[lane + 64], g4[lane + 96]);
                if (any) { acc.v0 = add4(acc.v0, r.v0); acc.v1 = add4(acc.v1, r.v1);
                           acc.v2 = add4(acc.v2, r.v2); acc.v3 = add4(acc.v3, r.v3); }
                else acc = r;
                any = true;
            }
        }

        // prefetch a(p+1)
        if (p + 1 < HW) {
            int pn = p + 1, pxn = pn / WWD, pyn = pn - pxn * WWD;
            int fx = (mode & 2) ? (HH - 1 - pxn) : pxn;
            int fy = (mode & 1) ? (WWD - 1 - pyn) : pyn;
            asmem[((p + 1) & 1) * CH + tid] =
                __ldg(Ab + (size_t)(fx * WWD + fy) * CH + tid);
        }

        if (p > 0) CLUSTER_WAIT();   // single wait: payloads(p-1) + ghist(p-2) visible

        // ---------- POST-WAIT ----------
        if (dcell >= 0) {            // deferred cell p-2
            const float4* g4 = (const float4*)(ghist + (dcell >> 3) * CH);
            C4 r = pool_cell(a0, a1, a2, a3,
                             g4[lane], g4[lane + 32], g4[lane + 64], g4[lane + 96]);
            if (any) { acc.v0 = add4(acc.v0, r.v0); acc.v1 = add4(acc.v1, r.v1);
                       acc.v2 = add4(acc.v2, r.v2); acc.v3 = add4(acc.v3, r.v3); }
            else acc = r;
            any = true;
        }
        if (any) {
            myslab[lane] = acc.v0; myslab[lane + 32] = acc.v1;
            myslab[lane + 64] = acc.v2; myslab[lane + 96] = acc.v3;
            if (lane == 0) flags[(p & 1) * 16 + wid] = 1;
        }

        if (p >= 1) reconstruct(p - 1, tid, rank, xslot, hvec, gHc);

        __syncthreads();   // S1: slab/flags + hvec ready

        // ---------- matvec G(p-1) rows R..R+3, scatter + JIT z-chunk ----------
        if (p >= 1) {
            const float4* hv4 = (const float4*)hvec;
            float4 h0 = hv4[lane],      h1 = hv4[lane + 32];
            float4 h2 = hv4[lane + 64], h3 = hv4[lane + 96];
            float v0, v1, v2, v3;
            v0 = warp_sum(dot4(wreg[0][0], h0) + dot4(wreg[0][1], h1) +
                          dot4(wreg[0][2], h2) + dot4(wreg[0][3], h3));
            v1 = warp_sum(dot4(wreg[1][0], h0) + dot4(wreg[1][1], h1) +
                          dot4(wreg[1][2], h2) + dot4(wreg[1][3], h3));
            v2 = warp_sum(dot4(wreg[2][0], h0) + dot4(wreg[2][1], h1) +
                          dot4(wreg[2][2], h2) + dot4(wreg[2][3], h3));
            v3 = warp_sum(dot4(wreg[3][0], h0) + dot4(wreg[3][1], h1) +
                          dot4(wreg[3][2], h2) + dot4(wreg[3][3], h3));
            float sv = (lane == 0) ? v0 : (lane == 1) ? v1 : (lane == 2) ? v2 : v3;
            if (lane < 4) {
                // scatter row R+lane of G(p-1) to owner CTA of cell p-1
                uint32_t la = sbase + OFF_GHIST +
                              (uint32_t)(((((p - 1) >> 3)) * CH + R + lane) * 4);
                st_cluster_f32(la, (uint32_t)((p - 1) & 7), sv);
                if (py >= 1) {   // JIT z-chunk for cell p-1 in window(p)
                    float a_s = asmem[(p & 1) * CH + R + lane];
                    zbuf[4 * wid + lane] = fmaxf(a_s + sv, 0.f);
                }
            }
        }
        __syncthreads();   // S2: zbuf ready

        const bool jit = (p >= 1) && (py >= 1);
        float zt = 0.f;
        if (jit && tid < 64) {
            zt = zbuf[tid];
            float wm = warp_max(zt);
            if (lane == 0) scr[wid] = wm;
        }

        // ---------- CTA sparse reduce -> broadcast partial ----------
        {
            const int* fl = flags + (p & 1) * 16;
            float part = 0.f;
#pragma unroll
            for (int w = 0; w < 16; w++)
                if (fl[w]) part += slab[w * CH + tid];
            uint32_t la = sbase + OFF_XSLOT +
                          (uint32_t)((((p & 1) * 8 + rank) * PAY + tid) * 4);
#pragma unroll
            for (int d = 0; d < 8; d++) st_cluster_f32(la, (uint32_t)d, part);
        }
        if (tid < 16) flags[((p + 1) & 1) * 16 + tid] = 0;
        __syncthreads();   // S3: scr (warp maxes) ready

        if (jit && tid < 64) {
            float m = fmaxf(scr[0], scr[1]);
            float e = __expf(zt - m);
            float n = zt * e;
            uint32_t la = sbase + OFF_XSLOT +
                          (uint32_t)((((p & 1) * 8 + rank) * PAY + 512 + tid) * 4);
#pragma unroll
            for (int d = 0; d < 8; d++) st_cluster_f32(la, (uint32_t)d, n);
            float se = warp_sum(e);
            if (lane == 0) scr[2 + wid] = se;
        }
        __syncthreads();   // S4: scr (warp expsums) ready

        if (jit && tid == 0) {
            float m = fmaxf(scr[0], scr[1]);
            float s = scr[2] + scr[3];
            uint32_t lam = sbase + OFF_XSLOT +
                           (uint32_t)((((p & 1) * 8 + rank) * PAY + 576) * 4);
            uint32_t las = lam + 4;
#pragma unroll
            for (int d = 0; d < 8; d++) {
                st_cluster_f32(lam, (uint32_t)d, m);
                st_cluster_f32(las, (uint32_t)d, s);
            }
        }
        CLUSTER_ARRIVE();  // single release: payload(p) + ghist scatter(p-1)
        __syncthreads();   // S5: protect slab/zbuf/scr reuse next iteration
    }

    CLUSTER_WAIT();        // final generation: payload(HW-1) visible
    reconstruct(HW - 1, tid, rank, xslot, hvec, gHc);
}

// ---------------------------------------------------------------------------
// Fused epilogue: Y = Wo @ (sum_m Hv) + 4*b_out, then channel softmax -> out
// ---------------------------------------------------------------------------
__global__ __launch_bounds__(NTHR) void epilogue_kernel(
    const float* __restrict__ Wo, const float* __restrict__ b_out,
    float* __restrict__ out) {
    __shared__ float hs[4 * 520];
    __shared__ float red[16];
    const int tid = threadIdx.x;
    const int wid = tid >> 5, lane = tid & 31;
    const int b   = blockIdx.x / 49;
    const int p0  = (blockIdx.x % 49) * 4;
#pragma unroll
    for (int j = 0; j < 4; j++) {
        float s = 0.f;
#pragma unroll
        for (int m = 0; m < 4; m++)
            s += g_Hv[((size_t)(m * 2 + b) * HW + p0 + j) * CH + tid];
        hs[j * 520 + tid] = s;
    }
    __syncthreads();
    const float4* w4 = (const float4*)(Wo + (size_t)tid * CH);
    float acc[4] = {0.f, 0.f, 0.f, 0.f};
    for (int k4 = 0; k4 < CH / 4; k4++) {
        float4 w = w4[k4];
#pragma unroll
        for (int j = 0; j < 4; j++) {
            float4 h = *(const float4*)(hs + j * 520 + 4 * k4);
            acc[j] += w.x * h.x + w.y * h.y + w.z * h.z + w.w * h.w;
        }
    }
    float bo = 4.f * b_out[tid];
#pragma unroll
    for (int j = 0; j < 4; j++) acc[j] += bo;

#pragma unroll
    for (int j = 0; j < 4; j++) {
        float m = warp_max(acc[j]);
        if (lane == 0) red[wid] = m;
        __syncthreads();
        float mm = red[0];
#pragma unroll
        for (int k = 1; k < 16; k++) mm = fmaxf(mm, red[k]);
        float e = __expf(acc[j] - mm);
        __syncthreads();
        float s = warp_sum(e);
        if (lane == 0) red[wid] = s;
        __syncthreads();
        float ss = 0.f;
#pragma unroll
        for (int k = 0; k < 16; k++) ss += red[k];
        out[((size_t)b * CH + tid) * HW + p0 + j] = e / ss;
        __syncthreads();
    }
}

extern "C" void kernel_launch(void* const* d_in, const int* in_sizes, int n_in,
                              void* d_out, int out_size) {
    const float* input = (const float*)d_in[0];
    const float* Wx    = (const float*)d_in[1];
    const float* Wh    = (const float*)d_in[2];
    const float* b_in  = (const float*)d_in[3];
    const float* Wo    = (const float*)d_in[4];
    const float* b_out = (const float*)d_in[5];
    float* out = (float*)d_out;
    (void)in_sizes; (void)n_in; (void)out_size;

    cudaFuncSetAttribute(scan_kernel,
                         cudaFuncAttributeMaxDynamicSharedMemorySize, SMEM_SZ);

    prologue_kernel<<<98, NTHR>>>(input, Wx, b_in);
    scan_kernel<<<NCHAIN * CLUS, NTHR, SMEM_SZ>>>(Wh);
    epilogue_kernel<<<98, NTHR>>>(Wo, b_out, out);
}